// round 15
// baseline (speedup 1.0000x reference)
#include <cuda_runtime.h>
#include <cuda_fp16.h>
#include <math.h>
#include <cstdint>

#define NROWS 8192
#define DIN   1024
#define DHID  4096
#define DOUT  1024

// half ping-pong activation buffers
__device__ __half g_h0[NROWS * DHID];
__device__ __half g_h1[NROWS * DHID];
// fp32 final GEMM output
__device__ float g_y3[NROWS * DOUT];
// fp16 weights
__device__ __half g_w1h[DHID * DIN];
__device__ __half g_w2h[DHID * DHID];
__device__ __half g_w3h[DOUT * DHID];
// per-row sum-of-squares (spatial part) after GEMM1 / GEMM2
__device__ float g_ss1[NROWS];
__device__ float g_ss2[NROWS];

// ───────────────────────── low-level helpers ─────────────────────────
__device__ __forceinline__ uint32_t smem_u32(const void* p) {
    uint32_t a;
    asm("{ .reg .u64 t; cvta.to.shared.u64 t, %1; cvt.u32.u64 %0, t; }" : "=r"(a) : "l"(p));
    return a;
}
__device__ __forceinline__ void ldsm_x4(uint32_t& r0, uint32_t& r1, uint32_t& r2, uint32_t& r3,
                                        uint32_t addr) {
    asm volatile("ldmatrix.sync.aligned.m8n8.x4.shared.b16 {%0,%1,%2,%3}, [%4];"
                 : "=r"(r0), "=r"(r1), "=r"(r2), "=r"(r3) : "r"(addr));
}
__device__ __forceinline__ void mma_f16(float& d0, float& d1, float& d2, float& d3,
                                        uint32_t a0, uint32_t a1, uint32_t a2, uint32_t a3,
                                        uint32_t b0, uint32_t b1) {
    asm volatile(
        "mma.sync.aligned.m16n8k16.row.col.f32.f16.f16.f32 "
        "{%0,%1,%2,%3}, {%4,%5,%6,%7}, {%8,%9}, {%0,%1,%2,%3};"
        : "+f"(d0), "+f"(d1), "+f"(d2), "+f"(d3)
        : "r"(a0), "r"(a1), "r"(a2), "r"(a3), "r"(b0), "r"(b1));
}
__device__ __forceinline__ uint32_t hmul2_u(uint32_t a, uint32_t f) {
    __half2 r = __hmul2(*reinterpret_cast<__half2*>(&a), *reinterpret_cast<__half2*>(&f));
    return *reinterpret_cast<uint32_t*>(&r);
}
#define CP_ASYNC16(dst, src) \
    asm volatile("cp.async.cg.shared.global [%0], [%1], 16;\n" :: "r"(dst), "l"(src))
#define CP_COMMIT()  asm volatile("cp.async.commit_group;\n" ::: "memory")
#define CP_WAIT1()   asm volatile("cp.async.wait_group 1;\n" ::: "memory")
#define CP_WAIT0()   asm volatile("cp.async.wait_group 0;\n" ::: "memory")

__device__ __forceinline__ uint32_t pack_h2(float a, float b) {
    __half2 h = __floats2half2_rn(a, b);
    return *reinterpret_cast<uint32_t*>(&h);
}

// ───────────────────────── elementwise kernels ─────────────────────────
__device__ __forceinline__ float block_reduce_sum(float v) {
    __shared__ float sh[33];
    int lane = threadIdx.x & 31;
    int wid  = threadIdx.x >> 5;
    #pragma unroll
    for (int o = 16; o > 0; o >>= 1) v += __shfl_down_sync(0xffffffffu, v, o);
    if (lane == 0) sh[wid] = v;
    __syncthreads();
    if (wid == 0) {
        float t = (lane < (int)(blockDim.x >> 5)) ? sh[lane] : 0.0f;
        #pragma unroll
        for (int o = 16; o > 0; o >>= 1) t += __shfl_down_sync(0xffffffffu, t, o);
        if (lane == 0) sh[32] = t;
    }
    __syncthreads();
    return sh[32];
}

__global__ __launch_bounds__(512) void zero_ss_kernel(float* __restrict__ a,
                                                      float* __restrict__ b) {
    int i = blockIdx.x * blockDim.x + threadIdx.x;
    if (i < NROWS) { a[i] = 0.0f; b[i] = 0.0f; }
}

// fp32 -> fp16 weight conversion
__global__ __launch_bounds__(256) void w2h_kernel(const float4* __restrict__ in,
                                                  uint2* __restrict__ out, int n4) {
    int i = blockIdx.x * blockDim.x + threadIdx.x;
    if (i < n4) {
        float4 v = in[i];
        uint2 o;
        o.x = pack_h2(v.x, v.y);
        o.y = pack_h2(v.z, v.w);
        out[i] = o;
    }
}

// t = logmap0(x) -> fp16
__global__ __launch_bounds__(256) void prep_kernel(const float* __restrict__ x,
                                                   __half* __restrict__ o) {
    int row = blockIdx.x;
    const float4* xr = reinterpret_cast<const float4*>(x + (size_t)row * DIN);
    uint2* orow = reinterpret_cast<uint2*>(o + (size_t)row * DIN);
    float4 v = xr[threadIdx.x];
    float ss;
    __shared__ float s_x0;
    if (threadIdx.x == 0) {
        s_x0 = v.x;
        ss = v.y * v.y + v.z * v.z + v.w * v.w;
    } else {
        ss = v.x * v.x + v.y * v.y + v.z * v.z + v.w * v.w;
    }
    float tot = block_reduce_sum(ss);
    float ns = fmaxf(sqrtf(tot), 1e-7f);
    float d = acoshf(fmaxf(s_x0, 1.0f + 1e-7f));
    float s = d / ns;
    float a0 = (threadIdx.x == 0) ? 0.0f : v.x * s;
    uint2 w;
    w.x = pack_h2(a0, v.y * s);
    w.y = pack_h2(v.z * s, v.w * s);
    orow[threadIdx.x] = w;
}

__global__ __launch_bounds__(256) void final_kernel(const float* __restrict__ y,
                                                    float* __restrict__ o) {
    int row = blockIdx.x;
    const float4* yr = reinterpret_cast<const float4*>(y + (size_t)row * DOUT);
    float4* orow = reinterpret_cast<float4*>(o + (size_t)row * DOUT);
    float4 v = yr[threadIdx.x];
    float ss;
    if (threadIdx.x == 0) ss = v.y * v.y + v.z * v.z + v.w * v.w;
    else                  ss = v.x * v.x + v.y * v.y + v.z * v.z + v.w * v.w;
    float n = fmaxf(sqrtf(block_reduce_sum(ss)), 1e-7f);
    float nc = fminf(n, 10.0f);
    float f = sinhf(nc) / n;
    float4 w;
    w.x = v.x * f; w.y = v.y * f; w.z = v.z * f; w.w = v.w * f;
    if (threadIdx.x == 0) w.x = coshf(nc);
    orow[threadIdx.x] = w;
}

// ───────────────────────── mma.sync fp16 GEMM with fused transform ────────
// C[M,Nn] = scale_rows(A)[M,K] @ B[Nn,K]^T + bias.
// SCALE_A: A rows scaled by f = min(n,10)/n with n = sqrt(ss_in[row]); A col 0
//          zeroed (Lorentz time slot).
// ACC_SS : epilogue accumulates per-row sum of squares of y (excluding col 0)
//          into ss_out via atomics.
// CTA 128x128x64, 8 warps, warp tile 64x32 (m16n8k16), 3-stage cp.async,
// one __syncthreads per mainloop iteration, 2 CTAs/SM.

#define BM 128
#define BN 128
#define BK 64
#define NSTAGE 3
#define STAGE_BYTES (128 * 128)
#define SMEM_TOTAL (2 * NSTAGE * STAGE_BYTES)   // 96 KB

template <typename OutT, bool SCALE_A, bool ACC_SS>
__global__ __launch_bounds__(256, 2) void gemm_mma_f16(const __half* __restrict__ A,
                                                       const __half* __restrict__ B,
                                                       const float* __restrict__ bias,
                                                       OutT* __restrict__ C,
                                                       const float* __restrict__ ss_in,
                                                       float* __restrict__ ss_out,
                                                       int M, int Nn, int K) {
    extern __shared__ char smem[];
    const uint32_t sbase = smem_u32(smem);
    const uint32_t sbase_b = sbase + NSTAGE * STAGE_BYTES;

    const int tid  = threadIdx.x;
    const int wid  = tid >> 5;
    const int lane = tid & 31;
    const int g    = lane >> 2;
    const int q    = lane & 3;

    const int bm = blockIdx.y * BM;
    const int bn = blockIdx.x * BN;
    const int wm = (wid & 1) * 64;
    const int wn = (wid >> 1) * 32;

    const int mat = lane >> 3, r8 = lane & 7;
    uint32_t a_rowoff[4], a_xor[4];
    const uint32_t a_chi = (uint32_t)(mat >> 1);
    #pragma unroll
    for (int mt = 0; mt < 4; mt++) {
        int row = wm + mt * 16 + (mat & 1) * 8 + r8;
        a_rowoff[mt] = (uint32_t)row * 128u;
        a_xor[mt] = (uint32_t)(row & 7);
    }
    uint32_t b_rowoff[2], b_xor[2];
    const uint32_t b_chi = (uint32_t)(mat & 1);
    #pragma unroll
    for (int np = 0; np < 2; np++) {
        int row = wn + np * 16 + (mat >> 1) * 8 + r8;
        b_rowoff[np] = (uint32_t)row * 128u;
        b_xor[np] = (uint32_t)(row & 7);
    }

    // Row scales for A fragments: af[mt][0],af[mt][2] -> row wm+mt*16+g;
    // af[mt][1],af[mt][3] -> row +8.
    uint32_t flo[4], fhi[4];
    if constexpr (SCALE_A) {
        #pragma unroll
        for (int mt = 0; mt < 4; mt++) {
            int r0 = bm + wm + mt * 16 + g;
            float s0 = ss_in[r0];
            float s1 = ss_in[r0 + 8];
            float n0 = fmaxf(sqrtf(s0), 1e-7f);
            float n1 = fmaxf(sqrtf(s1), 1e-7f);
            float f0 = fminf(n0, 10.0f) / n0;
            float f1 = fminf(n1, 10.0f) / n1;
            __half2 h0 = __float2half2_rn(f0);
            __half2 h1 = __float2half2_rn(f1);
            flo[mt] = *reinterpret_cast<uint32_t*>(&h0);
            fhi[mt] = *reinterpret_cast<uint32_t*>(&h1);
        }
    }

    float acc[4][4][4];
    #pragma unroll
    for (int i = 0; i < 4; i++)
        #pragma unroll
        for (int j = 0; j < 4; j++)
            #pragma unroll
            for (int r = 0; r < 4; r++) acc[i][j][r] = 0.0f;

    const int NC = K / BK;

    auto load_stage = [&](int c, int s) {
        const __half* Ab = A + (size_t)bm * K + (size_t)c * BK;
        const __half* Bb = B + (size_t)bn * K + (size_t)c * BK;
        const uint32_t ad = sbase + (uint32_t)s * STAGE_BYTES;
        const uint32_t bd = sbase_b + (uint32_t)s * STAGE_BYTES;
        #pragma unroll
        for (int it = 0; it < 4; it++) {
            int slot = tid + it * 256;
            int r = slot >> 3, c4 = slot & 7;
            uint32_t sw = (uint32_t)(c4 ^ (r & 7)) << 4;
            CP_ASYNC16(ad + (uint32_t)r * 128u + sw, Ab + (size_t)r * K + c4 * 8);
        }
        #pragma unroll
        for (int it = 0; it < 4; it++) {
            int slot = tid + it * 256;
            int r = slot >> 3, c4 = slot & 7;
            uint32_t sw = (uint32_t)(c4 ^ (r & 7)) << 4;
            CP_ASYNC16(bd + (uint32_t)r * 128u + sw, Bb + (size_t)r * K + c4 * 8);
        }
    };

    load_stage(0, 0);
    CP_COMMIT();
    load_stage(1, 1);
    CP_COMMIT();

    int sc = 0, sl = 2;
    for (int c = 0; c < NC; c++) {
        CP_WAIT1();
        __syncthreads();
        if constexpr (SCALE_A) {
            // zero A column 0 (k=0) in stage 0 before first use
            if (c == 0) {
                if (tid < 128) {
                    uint32_t addr = sbase + (uint32_t)tid * 128u + (((uint32_t)tid & 7u) << 4);
                    asm volatile("st.shared.u16 [%0], %1;" :: "r"(addr), "h"((unsigned short)0));
                }
                __syncthreads();
            }
        }
        if (c + 2 < NC) load_stage(c + 2, sl);
        CP_COMMIT();
        sl = (sl == NSTAGE - 1) ? 0 : sl + 1;

        const uint32_t ast = sbase + (uint32_t)sc * STAGE_BYTES;
        const uint32_t bst = sbase_b + (uint32_t)sc * STAGE_BYTES;
        sc = (sc == NSTAGE - 1) ? 0 : sc + 1;

        #pragma unroll
        for (int ks = 0; ks < 4; ks++) {
            uint32_t af[4][4];
            #pragma unroll
            for (int mt = 0; mt < 4; mt++) {
                uint32_t addr = ast + a_rowoff[mt] +
                                ((((uint32_t)ks * 2u + a_chi) ^ a_xor[mt]) << 4);
                ldsm_x4(af[mt][0], af[mt][1], af[mt][2], af[mt][3], addr);
            }
            if constexpr (SCALE_A) {
                #pragma unroll
                for (int mt = 0; mt < 4; mt++) {
                    af[mt][0] = hmul2_u(af[mt][0], flo[mt]);
                    af[mt][2] = hmul2_u(af[mt][2], flo[mt]);
                    af[mt][1] = hmul2_u(af[mt][1], fhi[mt]);
                    af[mt][3] = hmul2_u(af[mt][3], fhi[mt]);
                }
            }
            uint32_t bf[4][2];
            #pragma unroll
            for (int np = 0; np < 2; np++) {
                uint32_t addr = bst + b_rowoff[np] +
                                ((((uint32_t)ks * 2u + b_chi) ^ b_xor[np]) << 4);
                ldsm_x4(bf[2 * np][0], bf[2 * np][1], bf[2 * np + 1][0], bf[2 * np + 1][1], addr);
            }
            #pragma unroll
            for (int mt = 0; mt < 4; mt++)
                #pragma unroll
                for (int nt = 0; nt < 4; nt++)
                    mma_f16(acc[mt][nt][0], acc[mt][nt][1], acc[mt][nt][2], acc[mt][nt][3],
                            af[mt][0], af[mt][1], af[mt][2], af[mt][3],
                            bf[nt][0], bf[nt][1]);
        }
    }
    CP_WAIT0();

    // Epilogue: write y and (optionally) accumulate per-row sum of squares.
    #pragma unroll
    for (int mt = 0; mt < 4; mt++) {
        const int r0 = bm + wm + mt * 16 + g;
        float ss_lo = 0.0f, ss_hi = 0.0f;
        #pragma unroll
        for (int nt = 0; nt < 4; nt++) {
            const int c0 = bn + wn + nt * 8 + q * 2;
            float2 bv = *reinterpret_cast<const float2*>(bias + c0);
            float v0 = acc[mt][nt][0] + bv.x;
            float v1 = acc[mt][nt][1] + bv.y;
            float v2 = acc[mt][nt][2] + bv.x;
            float v3 = acc[mt][nt][3] + bv.y;
            if constexpr (ACC_SS) {
                if (c0 == 0) {            // exclude the Lorentz time column
                    ss_lo += v1 * v1;
                    ss_hi += v3 * v3;
                } else {
                    ss_lo += v0 * v0 + v1 * v1;
                    ss_hi += v2 * v2 + v3 * v3;
                }
            }
            if constexpr (sizeof(OutT) == 2) {
                *reinterpret_cast<uint32_t*>(&C[(size_t)r0 * Nn + c0]) = pack_h2(v0, v1);
                *reinterpret_cast<uint32_t*>(&C[(size_t)(r0 + 8) * Nn + c0]) = pack_h2(v2, v3);
            } else {
                float2 o0{v0, v1}, o1{v2, v3};
                *reinterpret_cast<float2*>(&C[(size_t)r0 * Nn + c0]) = o0;
                *reinterpret_cast<float2*>(&C[(size_t)(r0 + 8) * Nn + c0]) = o1;
            }
        }
        if constexpr (ACC_SS) {
            // reduce over the 4 q-lanes sharing this row
            ss_lo += __shfl_xor_sync(0xffffffffu, ss_lo, 1);
            ss_lo += __shfl_xor_sync(0xffffffffu, ss_lo, 2);
            ss_hi += __shfl_xor_sync(0xffffffffu, ss_hi, 1);
            ss_hi += __shfl_xor_sync(0xffffffffu, ss_hi, 2);
            if (q == 0) {
                atomicAdd(&ss_out[r0], ss_lo);
                atomicAdd(&ss_out[r0 + 8], ss_hi);
            }
        }
    }
}

// ───────────────────────── launch ─────────────────────────
extern "C" void kernel_launch(void* const* d_in, const int* in_sizes, int n_in,
                              void* d_out, int out_size) {
    const float* x  = (const float*)d_in[0];
    const float* W1 = (const float*)d_in[1];
    const float* b1 = (const float*)d_in[2];
    const float* W2 = (const float*)d_in[3];
    const float* b2 = (const float*)d_in[4];
    const float* W3 = (const float*)d_in[5];
    const float* b3 = (const float*)d_in[6];
    float* out = (float*)d_out;

    __half *h0, *h1, *w1h, *w2h, *w3h;
    float *y3, *ss1, *ss2;
    cudaGetSymbolAddress((void**)&h0, g_h0);
    cudaGetSymbolAddress((void**)&h1, g_h1);
    cudaGetSymbolAddress((void**)&y3, g_y3);
    cudaGetSymbolAddress((void**)&w1h, g_w1h);
    cudaGetSymbolAddress((void**)&w2h, g_w2h);
    cudaGetSymbolAddress((void**)&w3h, g_w3h);
    cudaGetSymbolAddress((void**)&ss1, g_ss1);
    cudaGetSymbolAddress((void**)&ss2, g_ss2);

    cudaFuncSetAttribute((const void*)gemm_mma_f16<__half, false, true>,
                         cudaFuncAttributeMaxDynamicSharedMemorySize, SMEM_TOTAL);
    cudaFuncSetAttribute((const void*)gemm_mma_f16<__half, true, true>,
                         cudaFuncAttributeMaxDynamicSharedMemorySize, SMEM_TOTAL);
    cudaFuncSetAttribute((const void*)gemm_mma_f16<float, true, false>,
                         cudaFuncAttributeMaxDynamicSharedMemorySize, SMEM_TOTAL);

    zero_ss_kernel<<<NROWS / 512, 512>>>(ss1, ss2);

    // fp16 weight conversion
    w2h_kernel<<<(DHID * DIN / 4 + 255) / 256, 256>>>((const float4*)W1, (uint2*)w1h, DHID * DIN / 4);
    w2h_kernel<<<(DHID * DHID / 4 + 255) / 256, 256>>>((const float4*)W2, (uint2*)w2h, DHID * DHID / 4);
    w2h_kernel<<<(DOUT * DHID / 4 + 255) / 256, 256>>>((const float4*)W3, (uint2*)w3h, DOUT * DHID / 4);

    // t1 = logmap0(x) -> fp16 h0
    prep_kernel<<<NROWS, 256>>>(x, h0);

    // y1 = t1 @ W1^T + b1 -> fp16 h1, row norms -> ss1
    {
        dim3 grid(DHID / BN, NROWS / BM);
        gemm_mma_f16<__half, false, true><<<grid, 256, SMEM_TOTAL>>>(
            h0, w1h, b1, h1, nullptr, ss1, NROWS, DHID, DIN);
    }
    // y2 = scale(y1) @ W2^T + b2 -> fp16 h0, row norms -> ss2
    {
        dim3 grid(DHID / BN, NROWS / BM);
        gemm_mma_f16<__half, true, true><<<grid, 256, SMEM_TOTAL>>>(
            h1, w2h, b2, h0, ss1, ss2, NROWS, DHID, DHID);
    }
    // y3 = scale(y2) @ W3^T + b3 -> fp32
    {
        dim3 grid(DOUT / BN, NROWS / BM);
        gemm_mma_f16<float, true, false><<<grid, 256, SMEM_TOTAL>>>(
            h0, w3h, b3, y3, ss2, nullptr, NROWS, DOUT, DHID);
    }
    final_kernel<<<NROWS, 256>>>(y3, out);
}